// round 15
// baseline (speedup 1.0000x reference)
#include <cuda_runtime.h>
#include <cstdint>

#define Bb 2
#define Nn 2048
#define Cc 384
#define Hh 6
#define Dd 64
#define BN 4096
#define C3 1152
#define BHh 12
#define SROW 2064

#define PHYS32(v) (((v) & ~31) | (((v) & 12) << 1) | (((v) & 16) >> 2) | ((v) & 3))

// ---- scratch ----
__device__ __align__(16) uint16_t g_xb[BN * Cc];   // bf16 x, perm16 layout
__device__ __align__(16) uint16_t g_wb[C3 * Cc];   // bf16 w_qkv, perm16 layout
__device__ __align__(16) int8_t g_wproj[Cc * Cc];  // int8 perm32
__device__ __align__(16) int8_t g_q[BHh * Nn * Dd];
__device__ __align__(16) int8_t g_k[BHh * Nn * Dd];
__device__ __align__(16) int8_t g_vT[BHh * Dd * Nn];
__device__ __align__(16) int8_t g_o[BN * Cc];

__device__ __forceinline__ int q8i(float v) {
    return __float2int_rn(fminf(fmaxf(v, -128.f), 127.f));
}
__device__ __forceinline__ int q8b(float v) {  // identical: rni + sat.s8
    int r;
    asm("cvt.rni.sat.s8.f32 %0, %1;" : "=r"(r) : "f"(v));
    return r;
}
__device__ __forceinline__ unsigned bfbits(int v) {
    return __float_as_uint((float)v) >> 16;
}

__device__ __forceinline__ void mma8(int* c, const unsigned* a, const unsigned* b) {
    asm volatile(
        "mma.sync.aligned.m16n8k32.row.col.s32.s8.s8.s32 "
        "{%0,%1,%2,%3}, {%4,%5,%6,%7}, {%8,%9}, {%0,%1,%2,%3};\n"
        : "+r"(c[0]), "+r"(c[1]), "+r"(c[2]), "+r"(c[3])
        : "r"(a[0]), "r"(a[1]), "r"(a[2]), "r"(a[3]), "r"(b[0]), "r"(b[1]));
}
__device__ __forceinline__ void mmabf(float* c, const unsigned* a, const unsigned* b) {
    asm volatile(
        "mma.sync.aligned.m16n8k16.row.col.f32.bf16.bf16.f32 "
        "{%0,%1,%2,%3}, {%4,%5,%6,%7}, {%8,%9}, {%0,%1,%2,%3};\n"
        : "+f"(c[0]), "+f"(c[1]), "+f"(c[2]), "+f"(c[3])
        : "r"(a[0]), "r"(a[1]), "r"(a[2]), "r"(a[3]), "r"(b[0]), "r"(b[1]));
}

// ---------------- merged quantize kernel ----------------
__global__ void quant_all_k(const float* __restrict__ x,
                            const float* __restrict__ wqkv,
                            const float* __restrict__ wproj,
                            const float* __restrict__ a_a,
                            const float* __restrict__ a_w,
                            const float* __restrict__ a_pw) {
    int b = blockIdx.x;
    if (b >= 1968) {  // w_proj -> int8 perm32
        int i = (b - 1968) * 256 + threadIdx.x;
        float ia = 1.f / __ldg(a_pw);
        float4 v = ((const float4*)wproj)[i];
        char4 r;
        r.x = (char)q8i(v.x * ia); r.y = (char)q8i(v.y * ia);
        r.z = (char)q8i(v.z * ia); r.w = (char)q8i(v.w * ia);
        int c4 = (i * 4) % Cc;
        int row = (i * 4) / Cc;
        int pc = (c4 & ~31) + (((c4 >> 2) & 3) << 3) + (((c4 >> 4) & 1) << 2);
        *(char4*)(g_wproj + row * Cc + pc) = r;
        return;
    }
    const float* src;
    uint16_t* dst;
    const float* al;
    int i;
    if (b < 1536) { src = x;    dst = g_xb; al = a_a; i = b * 256 + threadIdx.x; }
    else          { src = wqkv; dst = g_wb; al = a_w; i = (b - 1536) * 256 + threadIdx.x; }
    float ia = 1.f / __ldg(al);
    float4 v = ((const float4*)src)[i];
    int v0 = q8i(v.x * ia), v1 = q8i(v.y * ia), v2 = q8i(v.z * ia), v3 = q8i(v.w * ia);
    int c4 = (i * 4) % Cc;
    int row = (i * 4) / Cc;
    int gbase = c4 & ~15, cr = c4 & 15;
    int p0 = gbase + ((cr & 7) >> 1) * 4 + ((cr >> 3) << 1);
    int cr2 = cr + 2;
    int p1 = gbase + ((cr2 & 7) >> 1) * 4 + ((cr2 >> 3) << 1);
    *(unsigned*)(dst + row * Cc + p0) = bfbits(v0) | (bfbits(v1) << 16);
    *(unsigned*)(dst + row * Cc + p1) = bfbits(v2) | (bfbits(v3) << 16);
}

// ---- bf16 fragment loaders (perm16) ----
__device__ __forceinline__ void ldAb(unsigned a[2][4], const uint16_t* base, int k0) {
#pragma unroll
    for (int mt = 0; mt < 2; mt++) {
        const uint16_t* ap = base + mt * 16 * Cc + k0;
        uint2 lo = *(const uint2*)ap;
        uint2 hi = *(const uint2*)(ap + 8 * Cc);
        a[mt][0] = lo.x; a[mt][2] = lo.y;
        a[mt][1] = hi.x; a[mt][3] = hi.y;
    }
}
__device__ __forceinline__ void ldBb(unsigned b[8][2], const uint16_t* base, int k0) {
#pragma unroll
    for (int nt = 0; nt < 8; nt++) {
        uint2 bv = *(const uint2*)(base + nt * 8 * Cc + k0);
        b[nt][0] = bv.x; b[nt][1] = bv.y;
    }
}

// ---------------- GEMM1 (bf16 HMMA, round-11 verbatim) ----------------
__global__ void __launch_bounds__(256) gemm_qkv_k(
    const float* al_a, const float* al_w,
    const float* al_q, const float* al_k, const float* al_v) {
    const int bm = blockIdx.y * 128;
    const int bn = blockIdx.x * 128;
    const int wid = threadIdx.x >> 5;
    const int lane = threadIdx.x & 31;
    const int wm = (wid & 3) * 32;
    const int wn = (wid >> 2) * 64;
    const int lr = lane >> 2;
    const int q4 = (lane & 3) * 4;
    const uint16_t* abase = g_xb + (bm + wm + lr) * Cc + q4;
    const uint16_t* bbase = g_wb + (bn + wn + lr) * Cc + q4;

    float c[2][8][4];
#pragma unroll
    for (int i = 0; i < 2; i++)
#pragma unroll
        for (int j = 0; j < 8; j++)
#pragma unroll
            for (int t = 0; t < 4; t++) c[i][j][t] = 0.f;

    unsigned A0[2][4], A1[2][4], B0[8][2], B1[8][2];
    ldAb(A0, abase, 0);
    ldBb(B0, bbase, 0);
#pragma unroll 1
    for (int k0 = 0; k0 < Cc; k0 += 32) {
        ldAb(A1, abase, k0 + 16);
        ldBb(B1, bbase, k0 + 16);
#pragma unroll
        for (int nt = 0; nt < 8; nt++) {
            mmabf(c[0][nt], A0[0], B0[nt]);
            mmabf(c[1][nt], A0[1], B0[nt]);
        }
        if (k0 + 32 < Cc) {
            ldAb(A0, abase, k0 + 32);
            ldBb(B0, bbase, k0 + 32);
        }
#pragma unroll
        for (int nt = 0; nt < 8; nt++) {
            mmabf(c[0][nt], A1[0], B1[nt]);
            mmabf(c[1][nt], A1[1], B1[nt]);
        }
    }

    const float c1 = __ldg(al_a) * __ldg(al_w);
    const float iq = c1 / __ldg(al_q), ik = c1 / __ldg(al_k), iv = c1 / __ldg(al_v);
#pragma unroll
    for (int mt = 0; mt < 2; mt++)
#pragma unroll
        for (int nt = 0; nt < 8; nt++)
#pragma unroll
            for (int j = 0; j < 4; j++) {
                int row = bm + wm + mt * 16 + lr + ((j >> 1) << 3);
                int col = bn + wn + nt * 8 + ((lane & 3) << 1) + (j & 1);
                float f = c[mt][nt][j];
                int b = row >> 11, n = row & (Nn - 1);
                int which = col / Cc;
                int cr = col - which * Cc;
                int h = cr >> 6, d = cr & 63;
                if (which == 0)
                    g_q[((b * Hh + h) * Nn + n) * Dd + PHYS32(d)] = (int8_t)q8i(f * iq);
                else if (which == 1)
                    g_k[((b * Hh + h) * Nn + n) * Dd + PHYS32(d)] = (int8_t)q8i(f * ik);
                else
                    g_vT[((b * Hh + h) * Dd + d) * Nn + PHYS32(n)] = (int8_t)q8i(f * iv);
            }
}

// ---------------- fused attention: 256 threads, 3 CTAs/SM (24 warps/SM) ----
#define LUTF_OFF (32 * SROW)            // 66048
#define LUT8_OFF (LUTF_OFF + 1024)      // 67072: 8 warps * 256
#define SUMS_OFF (LUT8_OFF + 2048)      // 69120: float[8][32]
#define INVR_OFF (SUMS_OFF + 1024)      // 70144
#define SMEM_SZ  (INVR_OFF + 128)       // 70272 (x3 = 211KB <= 228KB)

__device__ __forceinline__ void qk_ldK(unsigned b[4][2][2], const int8_t* kp, int col0) {
#pragma unroll
    for (int nt = 0; nt < 4; nt++)
#pragma unroll
        for (int ks = 0; ks < 2; ks++) {
            uint2 bv = *(const uint2*)(kp + (col0 + nt * 8) * Dd + ks * 32);
            b[nt][ks][0] = bv.x; b[nt][ks][1] = bv.y;
        }
}
__device__ __forceinline__ void qk_chunk(const unsigned a[2][2][4], const unsigned b[4][2][2],
                                         int col0, int lr, int lane, float c2i,
                                         const float* lutf, float* rsum, int8_t* s_s) {
    int c[2][4][4];
#pragma unroll
    for (int i = 0; i < 2; i++)
#pragma unroll
        for (int j = 0; j < 4; j++)
#pragma unroll
            for (int t = 0; t < 4; t++) c[i][j][t] = 0;
#pragma unroll
    for (int nt = 0; nt < 4; nt++)
#pragma unroll
        for (int ks = 0; ks < 2; ks++) {
            mma8(c[0][nt], a[0][ks], b[nt][ks]);
            mma8(c[1][nt], a[1][ks], b[nt][ks]);
        }
#pragma unroll
    for (int mt = 0; mt < 2; mt++)
#pragma unroll
        for (int nt = 0; nt < 4; nt++)
#pragma unroll
            for (int jj = 0; jj < 2; jj++) {
                int row = mt * 16 + lr + jj * 8;
                int col = col0 + nt * 8 + ((lane & 3) << 1);
                int pc = PHYS32(col);
                int v0 = q8b((float)c[mt][nt][jj * 2 + 0] * c2i);
                int v1 = q8b((float)c[mt][nt][jj * 2 + 1] * c2i);
                rsum[mt * 2 + jj] += lutf[v0 & 255] + lutf[v1 & 255];
                char2 o;
                o.x = (char)v0; o.y = (char)v1;
                *(char2*)(s_s + row * SROW + pc) = o;
            }
}
__device__ __forceinline__ void pv_ldV2(unsigned v[2][2], const int8_t* vt, int k0) {
#pragma unroll
    for (int nt = 0; nt < 2; nt++) {
        uint2 bv = *(const uint2*)(vt + nt * 8 * Nn + k0);
        v[nt][0] = bv.x; v[nt][1] = bv.y;
    }
}

__global__ void __launch_bounds__(256, 3) attn_fused_k(
    const float* al_q, const float* al_k, const float* al_attn, const float* al_attn2,
    const float* al_v, const float* al_pa) {
    extern __shared__ int8_t s_s[];
    const int bh = blockIdx.y;
    const int rb = blockIdx.x * 32;
    const int8_t* qp = g_q + bh * Nn * Dd;
    const int tid = threadIdx.x;
    const int wid = tid >> 5;
    const int lane = tid & 31;
    const int lr = lane >> 2;
    const int q8 = (lane & 3) << 3;
    const float aAttn = __ldg(al_attn);
    const float c2i = __ldg(al_q) * __ldg(al_k) * 0.125f / aAttn;
    const float a2 = __ldg(al_attn2);
    const int8_t* kp = g_k + bh * Nn * Dd + lr * Dd + q8;

    float* lutf = (float*)(s_s + LUTF_OFF);
    if (tid < 256) {
        const float k2 = aAttn * 1.44269504f;
        lutf[tid] = exp2f(k2 * (float)(char)tid);
    }

    unsigned a[2][2][4];
#pragma unroll
    for (int mt = 0; mt < 2; mt++)
#pragma unroll
        for (int ks = 0; ks < 2; ks++) {
            const int8_t* ap = qp + (rb + mt * 16 + lr) * Dd + ks * 32 + q8;
            uint2 lo = *(const uint2*)ap;
            uint2 hi = *(const uint2*)(ap + 8 * Dd);
            a[mt][ks][0] = lo.x; a[mt][ks][2] = lo.y;
            a[mt][ks][1] = hi.x; a[mt][ks][3] = hi.y;
        }
    __syncthreads();

    // ---- Phase A: 256-col stripe per warp (8 warps), K double-buffered ----
    float rsum[4] = {0.f, 0.f, 0.f, 0.f};
    const int nbase = wid * 256;
    {
        unsigned B0[4][2][2], B1[4][2][2];
        qk_ldK(B0, kp, nbase);
#pragma unroll 1
        for (int nc = 0; nc < 256; nc += 64) {
            qk_ldK(B1, kp, nbase + nc + 32);
            qk_chunk(a, B0, nbase + nc, lr, lane, c2i, lutf, rsum, s_s);
            if (nc + 64 < 256) qk_ldK(B0, kp, nbase + nc + 64);
            qk_chunk(a, B1, nbase + nc + 32, lr, lane, c2i, lutf, rsum, s_s);
        }
    }
#pragma unroll
    for (int i = 0; i < 4; i++) {
        rsum[i] += __shfl_xor_sync(0xffffffffu, rsum[i], 1);
        rsum[i] += __shfl_xor_sync(0xffffffffu, rsum[i], 2);
    }
    if ((lane & 3) == 0) {
        float* smp = (float*)(s_s + SUMS_OFF) + wid * 32;
        smp[lr] = rsum[0]; smp[lr + 8] = rsum[1];
        smp[lr + 16] = rsum[2]; smp[lr + 24] = rsum[3];
    }
    __syncthreads();
    if (tid < 32) {
        const float* smp = (const float*)(s_s + SUMS_OFF);
        float t = 0.f;
#pragma unroll
        for (int w = 0; w < 8; w++) t += smp[w * 32 + tid];
        ((float*)(s_s + INVR_OFF))[tid] = 1.f / (t * a2);
    }
    __syncthreads();

    // ---- Phase B: 4 rows per warp ----
    {
        int8_t* lut8w = s_s + LUT8_OFF + wid * 256;
        const float* invr = (const float*)(s_s + INVR_OFF);
#pragma unroll 1
        for (int r = wid * 4; r < wid * 4 + 4; r++) {
            int8_t* srow = s_s + r * SROW;
            const float inv = invr[r];
            unsigned lo = 0, hi = 0;
#pragma unroll
            for (int j = 0; j < 8; j++) {
                int m = __float2int_rn(fminf(lutf[lane * 8 + j] * inv, 127.f));
                if (j < 4) lo |= (unsigned)(m & 255) << (8 * j);
                else       hi |= (unsigned)(m & 255) << (8 * (j - 4));
            }
            *(uint2*)(lut8w + lane * 8) = make_uint2(lo, hi);
            __syncwarp();
#pragma unroll
            for (int it = 0; it < 16; it++) {
                int8_t* p = srow + lane * 4 + it * 128;
                unsigned w = *(const unsigned*)p;
                unsigned r0 = (unsigned char)lut8w[w & 255];
                unsigned r1 = (unsigned char)lut8w[(w >> 8) & 255];
                unsigned r2 = (unsigned char)lut8w[(w >> 16) & 255];
                unsigned r3 = (unsigned char)lut8w[w >> 24];
                *(unsigned*)p = r0 | (r1 << 8) | (r2 << 16) | (r3 << 24);
            }
            __syncwarp();
        }
    }
    __syncthreads();

    // ---- Phase C: 16 rows x 16 cols per warp (2x4 warp grid), V double-buffered ----
    {
        const int8_t* Vt = g_vT + bh * Dd * Nn;
        const int wm2 = (wid & 1) * 16;
        const int wn2 = (wid >> 1) * 16;
        const int8_t* vt0 = Vt + (wn2 + lr) * Nn + q8;
        const int8_t* ap0 = s_s + (wm2 + lr) * SROW + q8;
        int c[2][4];
#pragma unroll
        for (int i = 0; i < 2; i++)
#pragma unroll
            for (int t = 0; t < 4; t++) c[i][t] = 0;

        unsigned V0[2][2], V1[2][2];
        pv_ldV2(V0, vt0, 0);
#pragma unroll 1
        for (int k0 = 0; k0 < Nn; k0 += 64) {
            pv_ldV2(V1, vt0, k0 + 32);
            {
                unsigned af[4];
                const int8_t* ap = ap0 + k0;
                uint2 lo = *(const uint2*)ap;
                uint2 hi = *(const uint2*)(ap + 8 * SROW);
                af[0] = lo.x; af[2] = lo.y;
                af[1] = hi.x; af[3] = hi.y;
                mma8(c[0], af, V0[0]);
                mma8(c[1], af, V0[1]);
            }
            if (k0 + 64 < Nn) pv_ldV2(V0, vt0, k0 + 64);
            {
                unsigned af[4];
                const int8_t* ap = ap0 + k0 + 32;
                uint2 lo = *(const uint2*)ap;
                uint2 hi = *(const uint2*)(ap + 8 * SROW);
                af[0] = lo.x; af[2] = lo.y;
                af[1] = hi.x; af[3] = hi.y;
                mma8(c[0], af, V1[0]);
                mma8(c[1], af, V1[1]);
            }
        }

        const float c3 = __ldg(al_attn2) * __ldg(al_v);
        const float ipa = c3 / __ldg(al_pa);
        const int b = bh / Hh, h = bh % Hh;
#pragma unroll
        for (int nt = 0; nt < 2; nt++)
#pragma unroll
            for (int j = 0; j < 4; j++) {
                int n = rb + wm2 + lr + ((j >> 1) << 3);
                int d = wn2 + nt * 8 + ((lane & 3) << 1) + (j & 1);
                g_o[(b * Nn + n) * Cc + h * Dd + PHYS32(d)] =
                    (int8_t)q8i((float)c[nt][j] * ipa);
            }
    }
}

// ---------------- GEMM2: 16x128 tiles (grid 768), reg double-buffered ----------------
__device__ __forceinline__ void ldB2i(unsigned b[2][2], const int8_t* base, int k0) {
#pragma unroll
    for (int nt = 0; nt < 2; nt++) {
        uint2 bv = *(const uint2*)(base + nt * 8 * Cc + k0);
        b[nt][0] = bv.x; b[nt][1] = bv.y;
    }
}
__global__ void __launch_bounds__(256) gemm_proj_k(
    float* __restrict__ out, const float* __restrict__ bias,
    const float* al_pa, const float* al_pw) {
    const int bm = blockIdx.y * 16;
    const int bn = blockIdx.x * 128;
    const int wid = threadIdx.x >> 5;
    const int lane = threadIdx.x & 31;
    const int wn = wid * 16;
    const int lr = lane >> 2;
    const int q8 = (lane & 3) << 3;
    const int8_t* abase = g_o + (bm + lr) * Cc + q8;
    const int8_t* bbase = g_wproj + (bn + wn + lr) * Cc + q8;

    int c[2][4];
#pragma unroll
    for (int j = 0; j < 2; j++)
#pragma unroll
        for (int t = 0; t < 4; t++) c[j][t] = 0;

    unsigned A0[4], A1[4], B0[2][2], B1[2][2];
    {
        uint2 lo = *(const uint2*)abase;
        uint2 hi = *(const uint2*)(abase + 8 * Cc);
        A0[0] = lo.x; A0[2] = lo.y; A0[1] = hi.x; A0[3] = hi.y;
    }
    ldB2i(B0, bbase, 0);
#pragma unroll 1
    for (int k0 = 0; k0 < Cc; k0 += 64) {
        {
            uint2 lo = *(const uint2*)(abase + k0 + 32);
            uint2 hi = *(const uint2*)(abase + k0 + 32 + 8 * Cc);
            A1[0] = lo.x; A1[2] = lo.y; A1[1] = hi.x; A1[3] = hi.y;
        }
        ldB2i(B1, bbase, k0 + 32);
        mma8(c[0], A0, B0[0]);
        mma8(c[1], A0, B0[1]);
        if (k0 + 64 < Cc) {
            uint2 lo = *(const uint2*)(abase + k0 + 64);
            uint2 hi = *(const uint2*)(abase + k0 + 64 + 8 * Cc);
            A0[0] = lo.x; A0[2] = lo.y; A0[1] = hi.x; A0[3] = hi.y;
            ldB2i(B0, bbase, k0 + 64);
        }
        mma8(c[0], A1, B1[0]);
        mma8(c[1], A1, B1[1]);
    }

    const float sc = __ldg(al_pa) * __ldg(al_pw);
#pragma unroll
    for (int nt = 0; nt < 2; nt++)
#pragma unroll
        for (int j = 0; j < 4; j++) {
            int row = bm + lr + ((j >> 1) << 3);
            int col = bn + wn + nt * 8 + ((lane & 3) << 1) + (j & 1);
            out[row * Cc + col] = (float)c[nt][j] * sc + __ldg(bias + col);
        }
}

extern "C" void kernel_launch(void* const* d_in, const int* in_sizes, int n_in,
                              void* d_out, int out_size) {
    const float* x        = (const float*)d_in[0];
    const float* w_qkv    = (const float*)d_in[1];
    const float* w_proj   = (const float*)d_in[2];
    const float* b_proj   = (const float*)d_in[3];
    const float* a_qkv_w  = (const float*)d_in[4];
    const float* a_qkv_a  = (const float*)d_in[5];
    const float* a_proj_w = (const float*)d_in[6];
    const float* a_proj_a = (const float*)d_in[7];
    const float* a_q      = (const float*)d_in[8];
    const float* a_k      = (const float*)d_in[9];
    const float* a_v      = (const float*)d_in[10];
    const float* a_attn   = (const float*)d_in[11];
    const float* a_attn2  = (const float*)d_in[12];
    float* out = (float*)d_out;

    quant_all_k<<<2112, 256>>>(x, w_qkv, w_proj, a_qkv_a, a_qkv_w, a_proj_w);

    gemm_qkv_k<<<dim3(C3 / 128, BN / 128), 256>>>(a_qkv_a, a_qkv_w, a_q, a_k, a_v);

    cudaFuncSetAttribute(attn_fused_k, cudaFuncAttributeMaxDynamicSharedMemorySize, SMEM_SZ);
    attn_fused_k<<<dim3(Nn / 32, BHh), 256, SMEM_SZ>>>(a_q, a_k, a_attn, a_attn2, a_v, a_proj_a);

    gemm_proj_k<<<dim3(Cc / 128, BN / 16), 256>>>(out, b_proj, a_proj_a, a_proj_w);
}

// round 16
// speedup vs baseline: 1.4144x; 1.4144x over previous
#include <cuda_runtime.h>
#include <cstdint>

#define Bb 2
#define Nn 2048
#define Cc 384
#define Hh 6
#define Dd 64
#define BN 4096
#define C3 1152
#define BHh 12
#define SROW 2064

#define PHYS32(v) (((v) & ~31) | (((v) & 12) << 1) | (((v) & 16) >> 2) | ((v) & 3))

// ---- scratch ----
__device__ __align__(16) uint16_t g_xb[BN * Cc];   // bf16 x, perm16 layout
__device__ __align__(16) uint16_t g_wb[C3 * Cc];   // bf16 w_qkv, perm16 layout
__device__ __align__(16) int8_t g_wproj[Cc * Cc];  // int8 perm32
__device__ __align__(16) int8_t g_q[BHh * Nn * Dd];
__device__ __align__(16) int8_t g_k[BHh * Nn * Dd];
__device__ __align__(16) int8_t g_vT[BHh * Dd * Nn];
__device__ __align__(16) int8_t g_o[BN * Cc];

__device__ __forceinline__ int q8i(float v) {
    return __float2int_rn(fminf(fmaxf(v, -128.f), 127.f));
}
__device__ __forceinline__ int q8b(float v) {  // identical: rni + sat.s8
    int r;
    asm("cvt.rni.sat.s8.f32 %0, %1;" : "=r"(r) : "f"(v));
    return r;
}
__device__ __forceinline__ unsigned bfbits(int v) {
    return __float_as_uint((float)v) >> 16;
}

__device__ __forceinline__ void mma8(int* c, const unsigned* a, const unsigned* b) {
    asm volatile(
        "mma.sync.aligned.m16n8k32.row.col.s32.s8.s8.s32 "
        "{%0,%1,%2,%3}, {%4,%5,%6,%7}, {%8,%9}, {%0,%1,%2,%3};\n"
        : "+r"(c[0]), "+r"(c[1]), "+r"(c[2]), "+r"(c[3])
        : "r"(a[0]), "r"(a[1]), "r"(a[2]), "r"(a[3]), "r"(b[0]), "r"(b[1]));
}
__device__ __forceinline__ void mmabf(float* c, const unsigned* a, const unsigned* b) {
    asm volatile(
        "mma.sync.aligned.m16n8k16.row.col.f32.bf16.bf16.f32 "
        "{%0,%1,%2,%3}, {%4,%5,%6,%7}, {%8,%9}, {%0,%1,%2,%3};\n"
        : "+f"(c[0]), "+f"(c[1]), "+f"(c[2]), "+f"(c[3])
        : "r"(a[0]), "r"(a[1]), "r"(a[2]), "r"(a[3]), "r"(b[0]), "r"(b[1]));
}

// ---------------- merged quantize kernel ----------------
__global__ void quant_all_k(const float* __restrict__ x,
                            const float* __restrict__ wqkv,
                            const float* __restrict__ wproj,
                            const float* __restrict__ a_a,
                            const float* __restrict__ a_w,
                            const float* __restrict__ a_pw) {
    int b = blockIdx.x;
    if (b >= 1968) {  // w_proj -> int8 perm32
        int i = (b - 1968) * 256 + threadIdx.x;
        float ia = 1.f / __ldg(a_pw);
        float4 v = ((const float4*)wproj)[i];
        char4 r;
        r.x = (char)q8i(v.x * ia); r.y = (char)q8i(v.y * ia);
        r.z = (char)q8i(v.z * ia); r.w = (char)q8i(v.w * ia);
        int c4 = (i * 4) % Cc;
        int row = (i * 4) / Cc;
        int pc = (c4 & ~31) + (((c4 >> 2) & 3) << 3) + (((c4 >> 4) & 1) << 2);
        *(char4*)(g_wproj + row * Cc + pc) = r;
        return;
    }
    const float* src;
    uint16_t* dst;
    const float* al;
    int i;
    if (b < 1536) { src = x;    dst = g_xb; al = a_a; i = b * 256 + threadIdx.x; }
    else          { src = wqkv; dst = g_wb; al = a_w; i = (b - 1536) * 256 + threadIdx.x; }
    float ia = 1.f / __ldg(al);
    float4 v = ((const float4*)src)[i];
    int v0 = q8i(v.x * ia), v1 = q8i(v.y * ia), v2 = q8i(v.z * ia), v3 = q8i(v.w * ia);
    int c4 = (i * 4) % Cc;
    int row = (i * 4) / Cc;
    int gbase = c4 & ~15, cr = c4 & 15;
    int p0 = gbase + ((cr & 7) >> 1) * 4 + ((cr >> 3) << 1);
    int cr2 = cr + 2;
    int p1 = gbase + ((cr2 & 7) >> 1) * 4 + ((cr2 >> 3) << 1);
    *(unsigned*)(dst + row * Cc + p0) = bfbits(v0) | (bfbits(v1) << 16);
    *(unsigned*)(dst + row * Cc + p1) = bfbits(v2) | (bfbits(v3) << 16);
}

// ---- bf16 fragment loaders (perm16) ----
__device__ __forceinline__ void ldAb1(unsigned a[4], const uint16_t* base, int k0) {
    uint2 lo = *(const uint2*)(base + k0);
    uint2 hi = *(const uint2*)(base + k0 + 8 * Cc);
    a[0] = lo.x; a[2] = lo.y; a[1] = hi.x; a[3] = hi.y;
}
__device__ __forceinline__ void ldBb(unsigned b[8][2], const uint16_t* base, int k0) {
#pragma unroll
    for (int nt = 0; nt < 8; nt++) {
        uint2 bv = *(const uint2*)(base + nt * 8 * Cc + k0);
        b[nt][0] = bv.x; b[nt][1] = bv.y;
    }
}

// ---------------- GEMM1 (bf16 HMMA): 64x128 tiles, grid 576 ----------------
__global__ void __launch_bounds__(256) gemm_qkv_k(
    const float* al_a, const float* al_w,
    const float* al_q, const float* al_k, const float* al_v) {
    const int bm = blockIdx.y * 64;
    const int bn = blockIdx.x * 128;
    const int wid = threadIdx.x >> 5;
    const int lane = threadIdx.x & 31;
    const int wm = (wid & 3) * 16;
    const int wn = (wid >> 2) * 64;
    const int lr = lane >> 2;
    const int q4 = (lane & 3) * 4;
    const uint16_t* abase = g_xb + (bm + wm + lr) * Cc + q4;
    const uint16_t* bbase = g_wb + (bn + wn + lr) * Cc + q4;

    float c[8][4];
#pragma unroll
    for (int j = 0; j < 8; j++)
#pragma unroll
        for (int t = 0; t < 4; t++) c[j][t] = 0.f;

    unsigned A0[4], A1[4], B0[8][2], B1[8][2];
    ldAb1(A0, abase, 0);
    ldBb(B0, bbase, 0);
#pragma unroll 1
    for (int k0 = 0; k0 < Cc; k0 += 32) {
        ldAb1(A1, abase, k0 + 16);
        ldBb(B1, bbase, k0 + 16);
#pragma unroll
        for (int nt = 0; nt < 8; nt++) mmabf(c[nt], A0, B0[nt]);
        if (k0 + 32 < Cc) {
            ldAb1(A0, abase, k0 + 32);
            ldBb(B0, bbase, k0 + 32);
        }
#pragma unroll
        for (int nt = 0; nt < 8; nt++) mmabf(c[nt], A1, B1[nt]);
    }

    const float c1 = __ldg(al_a) * __ldg(al_w);
    const float iq = c1 / __ldg(al_q), ik = c1 / __ldg(al_k), iv = c1 / __ldg(al_v);
#pragma unroll
    for (int nt = 0; nt < 8; nt++)
#pragma unroll
        for (int j = 0; j < 4; j++) {
            int row = bm + wm + lr + ((j >> 1) << 3);
            int col = bn + wn + nt * 8 + ((lane & 3) << 1) + (j & 1);
            float f = c[nt][j];
            int b = row >> 11, n = row & (Nn - 1);
            int which = col / Cc;
            int cr = col - which * Cc;
            int h = cr >> 6, d = cr & 63;
            if (which == 0)
                g_q[((b * Hh + h) * Nn + n) * Dd + PHYS32(d)] = (int8_t)q8i(f * iq);
            else if (which == 1)
                g_k[((b * Hh + h) * Nn + n) * Dd + PHYS32(d)] = (int8_t)q8i(f * ik);
            else
                g_vT[((b * Hh + h) * Dd + d) * Nn + PHYS32(n)] = (int8_t)q8i(f * iv);
        }
}

// ---------------- fused attention (round-14 verbatim): 128 threads, 3 CTAs/SM ----
#define LUTF_OFF (32 * SROW)
#define LUT8_OFF (LUTF_OFF + 1024)
#define SUMS_OFF (LUT8_OFF + 1024)
#define INVR_OFF (SUMS_OFF + 512)
#define SMEM_SZ  (INVR_OFF + 128)

__device__ __forceinline__ void qk_ldK(unsigned b[4][2][2], const int8_t* kp, int col0) {
#pragma unroll
    for (int nt = 0; nt < 4; nt++)
#pragma unroll
        for (int ks = 0; ks < 2; ks++) {
            uint2 bv = *(const uint2*)(kp + (col0 + nt * 8) * Dd + ks * 32);
            b[nt][ks][0] = bv.x; b[nt][ks][1] = bv.y;
        }
}
__device__ __forceinline__ void qk_chunk(const unsigned a[2][2][4], const unsigned b[4][2][2],
                                         int col0, int lr, int lane, float c2i,
                                         const float* lutf, float* rsum, int8_t* s_s) {
    int c[2][4][4];
#pragma unroll
    for (int i = 0; i < 2; i++)
#pragma unroll
        for (int j = 0; j < 4; j++)
#pragma unroll
            for (int t = 0; t < 4; t++) c[i][j][t] = 0;
#pragma unroll
    for (int nt = 0; nt < 4; nt++)
#pragma unroll
        for (int ks = 0; ks < 2; ks++) {
            mma8(c[0][nt], a[0][ks], b[nt][ks]);
            mma8(c[1][nt], a[1][ks], b[nt][ks]);
        }
#pragma unroll
    for (int mt = 0; mt < 2; mt++)
#pragma unroll
        for (int nt = 0; nt < 4; nt++)
#pragma unroll
            for (int jj = 0; jj < 2; jj++) {
                int row = mt * 16 + lr + jj * 8;
                int col = col0 + nt * 8 + ((lane & 3) << 1);
                int pc = PHYS32(col);
                int v0 = q8b((float)c[mt][nt][jj * 2 + 0] * c2i);
                int v1 = q8b((float)c[mt][nt][jj * 2 + 1] * c2i);
                rsum[mt * 2 + jj] += lutf[v0 & 255] + lutf[v1 & 255];
                char2 o;
                o.x = (char)v0; o.y = (char)v1;
                *(char2*)(s_s + row * SROW + pc) = o;
            }
}
__device__ __forceinline__ void pv_ldV(unsigned v[4][2], const int8_t* vt, int k0) {
#pragma unroll
    for (int nt = 0; nt < 4; nt++) {
        uint2 bv = *(const uint2*)(vt + nt * 8 * Nn + k0);
        v[nt][0] = bv.x; v[nt][1] = bv.y;
    }
}

__global__ void __launch_bounds__(128, 3) attn_fused_k(
    const float* al_q, const float* al_k, const float* al_attn, const float* al_attn2,
    const float* al_v, const float* al_pa) {
    extern __shared__ int8_t s_s[];
    const int bh = blockIdx.y;
    const int rb = blockIdx.x * 32;
    const int8_t* qp = g_q + bh * Nn * Dd;
    const int tid = threadIdx.x;
    const int wid = tid >> 5;
    const int lane = tid & 31;
    const int lr = lane >> 2;
    const int q8 = (lane & 3) << 3;
    const float aAttn = __ldg(al_attn);
    const float c2i = __ldg(al_q) * __ldg(al_k) * 0.125f / aAttn;
    const float a2 = __ldg(al_attn2);
    const int8_t* kp = g_k + bh * Nn * Dd + lr * Dd + q8;

    float* lutf = (float*)(s_s + LUTF_OFF);
    {
        const float k2 = aAttn * 1.44269504f;
        lutf[tid] = exp2f(k2 * (float)(char)tid);
        lutf[tid + 128] = exp2f(k2 * (float)(char)(tid + 128));
    }

    unsigned a[2][2][4];
#pragma unroll
    for (int mt = 0; mt < 2; mt++)
#pragma unroll
        for (int ks = 0; ks < 2; ks++) {
            const int8_t* ap = qp + (rb + mt * 16 + lr) * Dd + ks * 32 + q8;
            uint2 lo = *(const uint2*)ap;
            uint2 hi = *(const uint2*)(ap + 8 * Dd);
            a[mt][ks][0] = lo.x; a[mt][ks][2] = lo.y;
            a[mt][ks][1] = hi.x; a[mt][ks][3] = hi.y;
        }
    __syncthreads();

    float rsum[4] = {0.f, 0.f, 0.f, 0.f};
    const int nbase = wid * 512;
    {
        unsigned B0[4][2][2], B1[4][2][2];
        qk_ldK(B0, kp, nbase);
#pragma unroll 1
        for (int nc = 0; nc < 512; nc += 64) {
            qk_ldK(B1, kp, nbase + nc + 32);
            qk_chunk(a, B0, nbase + nc, lr, lane, c2i, lutf, rsum, s_s);
            if (nc + 64 < 512) qk_ldK(B0, kp, nbase + nc + 64);
            qk_chunk(a, B1, nbase + nc + 32, lr, lane, c2i, lutf, rsum, s_s);
        }
    }
#pragma unroll
    for (int i = 0; i < 4; i++) {
        rsum[i] += __shfl_xor_sync(0xffffffffu, rsum[i], 1);
        rsum[i] += __shfl_xor_sync(0xffffffffu, rsum[i], 2);
    }
    if ((lane & 3) == 0) {
        float* smp = (float*)(s_s + SUMS_OFF) + wid * 32;
        smp[lr] = rsum[0]; smp[lr + 8] = rsum[1];
        smp[lr + 16] = rsum[2]; smp[lr + 24] = rsum[3];
    }
    __syncthreads();
    if (tid < 32) {
        const float* smp = (const float*)(s_s + SUMS_OFF);
        float t = smp[tid] + smp[32 + tid] + smp[64 + tid] + smp[96 + tid];
        ((float*)(s_s + INVR_OFF))[tid] = 1.f / (t * a2);
    }
    __syncthreads();

    {
        int8_t* lut8w = s_s + LUT8_OFF + wid * 256;
        const float* invr = (const float*)(s_s + INVR_OFF);
#pragma unroll 1
        for (int r = wid * 8; r < wid * 8 + 8; r++) {
            int8_t* srow = s_s + r * SROW;
            const float inv = invr[r];
            unsigned lo = 0, hi = 0;
#pragma unroll
            for (int j = 0; j < 8; j++) {
                int m = __float2int_rn(fminf(lutf[lane * 8 + j] * inv, 127.f));
                if (j < 4) lo |= (unsigned)(m & 255) << (8 * j);
                else       hi |= (unsigned)(m & 255) << (8 * (j - 4));
            }
            *(uint2*)(lut8w + lane * 8) = make_uint2(lo, hi);
            __syncwarp();
#pragma unroll
            for (int it = 0; it < 16; it++) {
                int8_t* p = srow + lane * 4 + it * 128;
                unsigned w = *(const unsigned*)p;
                unsigned r0 = (unsigned char)lut8w[w & 255];
                unsigned r1 = (unsigned char)lut8w[(w >> 8) & 255];
                unsigned r2 = (unsigned char)lut8w[(w >> 16) & 255];
                unsigned r3 = (unsigned char)lut8w[w >> 24];
                *(unsigned*)p = r0 | (r1 << 8) | (r2 << 16) | (r3 << 24);
            }
            __syncwarp();
        }
    }
    __syncthreads();

    {
        const int8_t* Vt = g_vT + bh * Dd * Nn;
        const int wm2 = (wid & 1) * 16;
        const int wn2 = (wid >> 1) * 32;
        const int8_t* vt0 = Vt + (wn2 + lr) * Nn + q8;
        const int8_t* ap0 = s_s + (wm2 + lr) * SROW + q8;
        int c[4][4];
#pragma unroll
        for (int i = 0; i < 4; i++)
#pragma unroll
            for (int t = 0; t < 4; t++) c[i][t] = 0;

        unsigned V0[4][2], V1[4][2];
        pv_ldV(V0, vt0, 0);
#pragma unroll 1
        for (int k0 = 0; k0 < Nn; k0 += 64) {
            pv_ldV(V1, vt0, k0 + 32);
            {
                unsigned af[4];
                const int8_t* ap = ap0 + k0;
                uint2 lo = *(const uint2*)ap;
                uint2 hi = *(const uint2*)(ap + 8 * SROW);
                af[0] = lo.x; af[2] = lo.y;
                af[1] = hi.x; af[3] = hi.y;
#pragma unroll
                for (int nt = 0; nt < 4; nt++) mma8(c[nt], af, V0[nt]);
            }
            if (k0 + 64 < Nn) pv_ldV(V0, vt0, k0 + 64);
            {
                unsigned af[4];
                const int8_t* ap = ap0 + k0 + 32;
                uint2 lo = *(const uint2*)ap;
                uint2 hi = *(const uint2*)(ap + 8 * SROW);
                af[0] = lo.x; af[2] = lo.y;
                af[1] = hi.x; af[3] = hi.y;
#pragma unroll
                for (int nt = 0; nt < 4; nt++) mma8(c[nt], af, V1[nt]);
            }
        }

        const float c3 = __ldg(al_attn2) * __ldg(al_v);
        const float ipa = c3 / __ldg(al_pa);
        const int b = bh / Hh, h = bh % Hh;
#pragma unroll
        for (int nt = 0; nt < 4; nt++)
#pragma unroll
            for (int j = 0; j < 4; j++) {
                int n = rb + wm2 + lr + ((j >> 1) << 3);
                int d = wn2 + nt * 8 + ((lane & 3) << 1) + (j & 1);
                g_o[(b * Nn + n) * Cc + h * Dd + PHYS32(d)] =
                    (int8_t)q8i((float)c[nt][j] * ipa);
            }
    }
}

// ---------------- GEMM2 (round-14 verbatim): 32x128 tiles, grid 384 ----------------
__device__ __forceinline__ void ldB4i(unsigned b[4][2], const int8_t* base, int k0) {
#pragma unroll
    for (int nt = 0; nt < 4; nt++) {
        uint2 bv = *(const uint2*)(base + nt * 8 * Cc + k0);
        b[nt][0] = bv.x; b[nt][1] = bv.y;
    }
}
__global__ void __launch_bounds__(256) gemm_proj_k(
    float* __restrict__ out, const float* __restrict__ bias,
    const float* al_pa, const float* al_pw) {
    const int bm = blockIdx.y * 32;
    const int bn = blockIdx.x * 128;
    const int wid = threadIdx.x >> 5;
    const int lane = threadIdx.x & 31;
    const int wm = (wid & 1) * 16;
    const int wn = (wid >> 1) * 32;
    const int lr = lane >> 2;
    const int q8 = (lane & 3) << 3;
    const int8_t* abase = g_o + (bm + wm + lr) * Cc + q8;
    const int8_t* bbase = g_wproj + (bn + wn + lr) * Cc + q8;

    int c[4][4];
#pragma unroll
    for (int j = 0; j < 4; j++)
#pragma unroll
        for (int t = 0; t < 4; t++) c[j][t] = 0;

    unsigned A0[4], A1[4], B0[4][2], B1[4][2];
    {
        uint2 lo = *(const uint2*)abase;
        uint2 hi = *(const uint2*)(abase + 8 * Cc);
        A0[0] = lo.x; A0[2] = lo.y; A0[1] = hi.x; A0[3] = hi.y;
    }
    ldB4i(B0, bbase, 0);
#pragma unroll 1
    for (int k0 = 0; k0 < Cc; k0 += 64) {
        {
            uint2 lo = *(const uint2*)(abase + k0 + 32);
            uint2 hi = *(const uint2*)(abase + k0 + 32 + 8 * Cc);
            A1[0] = lo.x; A1[2] = lo.y; A1[1] = hi.x; A1[3] = hi.y;
        }
        ldB4i(B1, bbase, k0 + 32);
#pragma unroll
        for (int nt = 0; nt < 4; nt++) mma8(c[nt], A0, B0[nt]);
        if (k0 + 64 < Cc) {
            uint2 lo = *(const uint2*)(abase + k0 + 64);
            uint2 hi = *(const uint2*)(abase + k0 + 64 + 8 * Cc);
            A0[0] = lo.x; A0[2] = lo.y; A0[1] = hi.x; A0[3] = hi.y;
            ldB4i(B0, bbase, k0 + 64);
        }
#pragma unroll
        for (int nt = 0; nt < 4; nt++) mma8(c[nt], A1, B1[nt]);
    }

    const float sc = __ldg(al_pa) * __ldg(al_pw);
#pragma unroll
    for (int nt = 0; nt < 4; nt++)
#pragma unroll
        for (int j = 0; j < 4; j++) {
            int row = bm + wm + lr + ((j >> 1) << 3);
            int col = bn + wn + nt * 8 + ((lane & 3) << 1) + (j & 1);
            out[row * Cc + col] = (float)c[nt][j] * sc + __ldg(bias + col);
        }
}

extern "C" void kernel_launch(void* const* d_in, const int* in_sizes, int n_in,
                              void* d_out, int out_size) {
    const float* x        = (const float*)d_in[0];
    const float* w_qkv    = (const float*)d_in[1];
    const float* w_proj   = (const float*)d_in[2];
    const float* b_proj   = (const float*)d_in[3];
    const float* a_qkv_w  = (const float*)d_in[4];
    const float* a_qkv_a  = (const float*)d_in[5];
    const float* a_proj_w = (const float*)d_in[6];
    const float* a_proj_a = (const float*)d_in[7];
    const float* a_q      = (const float*)d_in[8];
    const float* a_k      = (const float*)d_in[9];
    const float* a_v      = (const float*)d_in[10];
    const float* a_attn   = (const float*)d_in[11];
    const float* a_attn2  = (const float*)d_in[12];
    float* out = (float*)d_out;

    quant_all_k<<<2112, 256>>>(x, w_qkv, w_proj, a_qkv_a, a_qkv_w, a_proj_w);

    gemm_qkv_k<<<dim3(C3 / 128, BN / 64), 256>>>(a_qkv_a, a_qkv_w, a_q, a_k, a_v);

    cudaFuncSetAttribute(attn_fused_k, cudaFuncAttributeMaxDynamicSharedMemorySize, SMEM_SZ);
    attn_fused_k<<<dim3(Nn / 32, BHh), 128, SMEM_SZ>>>(a_q, a_k, a_attn, a_attn2, a_v, a_proj_a);

    gemm_proj_k<<<dim3(Cc / 128, BN / 32), 256>>>(out, b_proj, a_proj_a, a_proj_w);
}

// round 17
// speedup vs baseline: 1.5498x; 1.0958x over previous
#include <cuda_runtime.h>
#include <cstdint>

#define Bb 2
#define Nn 2048
#define Cc 384
#define Hh 6
#define Dd 64
#define BN 4096
#define C3 1152
#define BHh 12
#define SROW 2064

#define PHYS32(v) (((v) & ~31) | (((v) & 12) << 1) | (((v) & 16) >> 2) | ((v) & 3))

// ---- scratch ----
__device__ __align__(16) uint16_t g_xb[BN * Cc];   // bf16 x, perm16 layout
__device__ __align__(16) uint16_t g_wb[C3 * Cc];   // bf16 w_qkv, perm16 layout
__device__ __align__(16) int8_t g_wproj[Cc * Cc];  // int8 perm32
__device__ __align__(16) int8_t g_q[BHh * Nn * Dd];
__device__ __align__(16) int8_t g_k[BHh * Nn * Dd];
__device__ __align__(16) int8_t g_vT[BHh * Dd * Nn];
__device__ __align__(16) int8_t g_o[BN * Cc];

// single-instruction round-to-nearest-even + saturate to s8
__device__ __forceinline__ int q8b(float v) {
    int r;
    asm("cvt.rni.sat.s8.f32 %0, %1;" : "=r"(r) : "f"(v));
    return r;
}
__device__ __forceinline__ unsigned bfbits(int v) {
    return __float_as_uint((float)v) >> 16;
}

__device__ __forceinline__ void mma8(int* c, const unsigned* a, const unsigned* b) {
    asm volatile(
        "mma.sync.aligned.m16n8k32.row.col.s32.s8.s8.s32 "
        "{%0,%1,%2,%3}, {%4,%5,%6,%7}, {%8,%9}, {%0,%1,%2,%3};\n"
        : "+r"(c[0]), "+r"(c[1]), "+r"(c[2]), "+r"(c[3])
        : "r"(a[0]), "r"(a[1]), "r"(a[2]), "r"(a[3]), "r"(b[0]), "r"(b[1]));
}
__device__ __forceinline__ void mmabf(float* c, const unsigned* a, const unsigned* b) {
    asm volatile(
        "mma.sync.aligned.m16n8k16.row.col.f32.bf16.bf16.f32 "
        "{%0,%1,%2,%3}, {%4,%5,%6,%7}, {%8,%9}, {%0,%1,%2,%3};\n"
        : "+f"(c[0]), "+f"(c[1]), "+f"(c[2]), "+f"(c[3])
        : "r"(a[0]), "r"(a[1]), "r"(a[2]), "r"(a[3]), "r"(b[0]), "r"(b[1]));
}

// ---------------- merged quantize kernel ----------------
__global__ void quant_all_k(const float* __restrict__ x,
                            const float* __restrict__ wqkv,
                            const float* __restrict__ wproj,
                            const float* __restrict__ a_a,
                            const float* __restrict__ a_w,
                            const float* __restrict__ a_pw) {
    int b = blockIdx.x;
    if (b >= 1968) {  // w_proj -> int8 perm32
        int i = (b - 1968) * 256 + threadIdx.x;
        float ia = 1.f / __ldg(a_pw);
        float4 v = ((const float4*)wproj)[i];
        char4 r;
        r.x = (char)q8b(v.x * ia); r.y = (char)q8b(v.y * ia);
        r.z = (char)q8b(v.z * ia); r.w = (char)q8b(v.w * ia);
        int c4 = (i * 4) % Cc;
        int row = (i * 4) / Cc;
        int pc = (c4 & ~31) + (((c4 >> 2) & 3) << 3) + (((c4 >> 4) & 1) << 2);
        *(char4*)(g_wproj + row * Cc + pc) = r;
        return;
    }
    const float* src;
    uint16_t* dst;
    const float* al;
    int i;
    if (b < 1536) { src = x;    dst = g_xb; al = a_a; i = b * 256 + threadIdx.x; }
    else          { src = wqkv; dst = g_wb; al = a_w; i = (b - 1536) * 256 + threadIdx.x; }
    float ia = 1.f / __ldg(al);
    float4 v = ((const float4*)src)[i];
    int v0 = q8b(v.x * ia), v1 = q8b(v.y * ia), v2 = q8b(v.z * ia), v3 = q8b(v.w * ia);
    int c4 = (i * 4) % Cc;
    int row = (i * 4) / Cc;
    int gbase = c4 & ~15, cr = c4 & 15;
    int p0 = gbase + ((cr & 7) >> 1) * 4 + ((cr >> 3) << 1);
    int cr2 = cr + 2;
    int p1 = gbase + ((cr2 & 7) >> 1) * 4 + ((cr2 >> 3) << 1);
    *(unsigned*)(dst + row * Cc + p0) = bfbits(v0) | (bfbits(v1) << 16);
    *(unsigned*)(dst + row * Cc + p1) = bfbits(v2) | (bfbits(v3) << 16);
}

// ---- bf16 fragment loaders (perm16) ----
__device__ __forceinline__ void ldAb(unsigned a[2][4], const uint16_t* base, int k0) {
#pragma unroll
    for (int mt = 0; mt < 2; mt++) {
        const uint16_t* ap = base + mt * 16 * Cc + k0;
        uint2 lo = *(const uint2*)ap;
        uint2 hi = *(const uint2*)(ap + 8 * Cc);
        a[mt][0] = lo.x; a[mt][2] = lo.y;
        a[mt][1] = hi.x; a[mt][3] = hi.y;
    }
}
__device__ __forceinline__ void ldBb(unsigned b[8][2], const uint16_t* base, int k0) {
#pragma unroll
    for (int nt = 0; nt < 8; nt++) {
        uint2 bv = *(const uint2*)(base + nt * 8 * Cc + k0);
        b[nt][0] = bv.x; b[nt][1] = bv.y;
    }
}

// ---------------- GEMM1 (bf16 HMMA): 128x128 tiles (reuse-optimal) ----------------
__global__ void __launch_bounds__(256) gemm_qkv_k(
    const float* al_a, const float* al_w,
    const float* al_q, const float* al_k, const float* al_v) {
    const int bm = blockIdx.y * 128;
    const int bn = blockIdx.x * 128;
    const int wid = threadIdx.x >> 5;
    const int lane = threadIdx.x & 31;
    const int wm = (wid & 3) * 32;
    const int wn = (wid >> 2) * 64;
    const int lr = lane >> 2;
    const int q4 = (lane & 3) * 4;
    const uint16_t* abase = g_xb + (bm + wm + lr) * Cc + q4;
    const uint16_t* bbase = g_wb + (bn + wn + lr) * Cc + q4;

    float c[2][8][4];
#pragma unroll
    for (int i = 0; i < 2; i++)
#pragma unroll
        for (int j = 0; j < 8; j++)
#pragma unroll
            for (int t = 0; t < 4; t++) c[i][j][t] = 0.f;

    unsigned A0[2][4], A1[2][4], B0[8][2], B1[8][2];
    ldAb(A0, abase, 0);
    ldBb(B0, bbase, 0);
#pragma unroll 1
    for (int k0 = 0; k0 < Cc; k0 += 32) {
        ldAb(A1, abase, k0 + 16);
        ldBb(B1, bbase, k0 + 16);
#pragma unroll
        for (int nt = 0; nt < 8; nt++) {
            mmabf(c[0][nt], A0[0], B0[nt]);
            mmabf(c[1][nt], A0[1], B0[nt]);
        }
        if (k0 + 32 < Cc) {
            ldAb(A0, abase, k0 + 32);
            ldBb(B0, bbase, k0 + 32);
        }
#pragma unroll
        for (int nt = 0; nt < 8; nt++) {
            mmabf(c[0][nt], A1[0], B1[nt]);
            mmabf(c[1][nt], A1[1], B1[nt]);
        }
    }

    const float c1 = __ldg(al_a) * __ldg(al_w);
    const float iq = c1 / __ldg(al_q), ik = c1 / __ldg(al_k), iv = c1 / __ldg(al_v);
#pragma unroll
    for (int mt = 0; mt < 2; mt++)
#pragma unroll
        for (int nt = 0; nt < 8; nt++)
#pragma unroll
            for (int j = 0; j < 4; j++) {
                int row = bm + wm + mt * 16 + lr + ((j >> 1) << 3);
                int col = bn + wn + nt * 8 + ((lane & 3) << 1) + (j & 1);
                float f = c[mt][nt][j];
                int b = row >> 11, n = row & (Nn - 1);
                int which = col / Cc;
                int cr = col - which * Cc;
                int h = cr >> 6, d = cr & 63;
                if (which == 0)
                    g_q[((b * Hh + h) * Nn + n) * Dd + PHYS32(d)] = (int8_t)q8b(f * iq);
                else if (which == 1)
                    g_k[((b * Hh + h) * Nn + n) * Dd + PHYS32(d)] = (int8_t)q8b(f * ik);
                else
                    g_vT[((b * Hh + h) * Dd + d) * Nn + PHYS32(n)] = (int8_t)q8b(f * iv);
            }
}

// ---------------- fused attention: 128 threads, 3 CTAs/SM ----------------
#define LUTF_OFF (32 * SROW)
#define LUT8_OFF (LUTF_OFF + 1024)
#define SUMS_OFF (LUT8_OFF + 1024)
#define INVR_OFF (SUMS_OFF + 512)
#define SMEM_SZ  (INVR_OFF + 128)

__device__ __forceinline__ void qk_ldK(unsigned b[4][2][2], const int8_t* kp, int col0) {
#pragma unroll
    for (int nt = 0; nt < 4; nt++)
#pragma unroll
        for (int ks = 0; ks < 2; ks++) {
            uint2 bv = *(const uint2*)(kp + (col0 + nt * 8) * Dd + ks * 32);
            b[nt][ks][0] = bv.x; b[nt][ks][1] = bv.y;
        }
}
__device__ __forceinline__ void qk_chunk(const unsigned a[2][2][4], const unsigned b[4][2][2],
                                         int col0, int lr, int lane, float c2i,
                                         const float* lutf, float* rsum, int8_t* s_s) {
    int c[2][4][4];
#pragma unroll
    for (int i = 0; i < 2; i++)
#pragma unroll
        for (int j = 0; j < 4; j++)
#pragma unroll
            for (int t = 0; t < 4; t++) c[i][j][t] = 0;
#pragma unroll
    for (int nt = 0; nt < 4; nt++)
#pragma unroll
        for (int ks = 0; ks < 2; ks++) {
            mma8(c[0][nt], a[0][ks], b[nt][ks]);
            mma8(c[1][nt], a[1][ks], b[nt][ks]);
        }
#pragma unroll
    for (int mt = 0; mt < 2; mt++)
#pragma unroll
        for (int nt = 0; nt < 4; nt++)
#pragma unroll
            for (int jj = 0; jj < 2; jj++) {
                int row = mt * 16 + lr + jj * 8;
                int col = col0 + nt * 8 + ((lane & 3) << 1);
                int pc = PHYS32(col);
                int v0 = q8b((float)c[mt][nt][jj * 2 + 0] * c2i);
                int v1 = q8b((float)c[mt][nt][jj * 2 + 1] * c2i);
                rsum[mt * 2 + jj] += lutf[v0 & 255] + lutf[v1 & 255];
                char2 o;
                o.x = (char)v0; o.y = (char)v1;
                *(char2*)(s_s + row * SROW + pc) = o;
            }
}
__device__ __forceinline__ void pv_ldV(unsigned v[4][2], const int8_t* vt, int k0) {
#pragma unroll
    for (int nt = 0; nt < 4; nt++) {
        uint2 bv = *(const uint2*)(vt + nt * 8 * Nn + k0);
        v[nt][0] = bv.x; v[nt][1] = bv.y;
    }
}

__global__ void __launch_bounds__(128, 3) attn_fused_k(
    const float* al_q, const float* al_k, const float* al_attn, const float* al_attn2,
    const float* al_v, const float* al_pa) {
    extern __shared__ int8_t s_s[];
    const int bh = blockIdx.y;
    const int rb = blockIdx.x * 32;
    const int8_t* qp = g_q + bh * Nn * Dd;
    const int tid = threadIdx.x;
    const int wid = tid >> 5;
    const int lane = tid & 31;
    const int lr = lane >> 2;
    const int q8 = (lane & 3) << 3;
    const float aAttn = __ldg(al_attn);
    const float c2i = __ldg(al_q) * __ldg(al_k) * 0.125f / aAttn;
    const float a2 = __ldg(al_attn2);
    const int8_t* kp = g_k + bh * Nn * Dd + lr * Dd + q8;

    float* lutf = (float*)(s_s + LUTF_OFF);
    {
        const float k2 = aAttn * 1.44269504f;
        lutf[tid] = exp2f(k2 * (float)(char)tid);
        lutf[tid + 128] = exp2f(k2 * (float)(char)(tid + 128));
    }

    unsigned a[2][2][4];
#pragma unroll
    for (int mt = 0; mt < 2; mt++)
#pragma unroll
        for (int ks = 0; ks < 2; ks++) {
            const int8_t* ap = qp + (rb + mt * 16 + lr) * Dd + ks * 32 + q8;
            uint2 lo = *(const uint2*)ap;
            uint2 hi = *(const uint2*)(ap + 8 * Dd);
            a[mt][ks][0] = lo.x; a[mt][ks][2] = lo.y;
            a[mt][ks][1] = hi.x; a[mt][ks][3] = hi.y;
        }
    __syncthreads();

    float rsum[4] = {0.f, 0.f, 0.f, 0.f};
    const int nbase = wid * 512;
    {
        unsigned B0[4][2][2], B1[4][2][2];
        qk_ldK(B0, kp, nbase);
#pragma unroll 1
        for (int nc = 0; nc < 512; nc += 64) {
            qk_ldK(B1, kp, nbase + nc + 32);
            qk_chunk(a, B0, nbase + nc, lr, lane, c2i, lutf, rsum, s_s);
            if (nc + 64 < 512) qk_ldK(B0, kp, nbase + nc + 64);
            qk_chunk(a, B1, nbase + nc + 32, lr, lane, c2i, lutf, rsum, s_s);
        }
    }
#pragma unroll
    for (int i = 0; i < 4; i++) {
        rsum[i] += __shfl_xor_sync(0xffffffffu, rsum[i], 1);
        rsum[i] += __shfl_xor_sync(0xffffffffu, rsum[i], 2);
    }
    if ((lane & 3) == 0) {
        float* smp = (float*)(s_s + SUMS_OFF) + wid * 32;
        smp[lr] = rsum[0]; smp[lr + 8] = rsum[1];
        smp[lr + 16] = rsum[2]; smp[lr + 24] = rsum[3];
    }
    __syncthreads();
    if (tid < 32) {
        const float* smp = (const float*)(s_s + SUMS_OFF);
        float t = smp[tid] + smp[32 + tid] + smp[64 + tid] + smp[96 + tid];
        ((float*)(s_s + INVR_OFF))[tid] = 1.f / (t * a2);
    }
    __syncthreads();

    {
        int8_t* lut8w = s_s + LUT8_OFF + wid * 256;
        const float* invr = (const float*)(s_s + INVR_OFF);
#pragma unroll 1
        for (int r = wid * 8; r < wid * 8 + 8; r++) {
            int8_t* srow = s_s + r * SROW;
            const float inv = invr[r];
            unsigned lo = 0, hi = 0;
#pragma unroll
            for (int j = 0; j < 8; j++) {
                int m = q8b(fminf(lutf[lane * 8 + j] * inv, 127.f));
                if (j < 4) lo |= (unsigned)(m & 255) << (8 * j);
                else       hi |= (unsigned)(m & 255) << (8 * (j - 4));
            }
            *(uint2*)(lut8w + lane * 8) = make_uint2(lo, hi);
            __syncwarp();
#pragma unroll
            for (int it = 0; it < 16; it++) {
                int8_t* p = srow + lane * 4 + it * 128;
                unsigned w = *(const unsigned*)p;
                unsigned r0 = (unsigned char)lut8w[w & 255];
                unsigned r1 = (unsigned char)lut8w[(w >> 8) & 255];
                unsigned r2 = (unsigned char)lut8w[(w >> 16) & 255];
                unsigned r3 = (unsigned char)lut8w[w >> 24];
                *(unsigned*)p = r0 | (r1 << 8) | (r2 << 16) | (r3 << 24);
            }
            __syncwarp();
        }
    }
    __syncthreads();

    {
        const int8_t* Vt = g_vT + bh * Dd * Nn;
        const int wm2 = (wid & 1) * 16;
        const int wn2 = (wid >> 1) * 32;
        const int8_t* vt0 = Vt + (wn2 + lr) * Nn + q8;
        const int8_t* ap0 = s_s + (wm2 + lr) * SROW + q8;
        int c[4][4];
#pragma unroll
        for (int i = 0; i < 4; i++)
#pragma unroll
            for (int t = 0; t < 4; t++) c[i][t] = 0;

        unsigned V0[4][2], V1[4][2];
        pv_ldV(V0, vt0, 0);
#pragma unroll 1
        for (int k0 = 0; k0 < Nn; k0 += 64) {
            pv_ldV(V1, vt0, k0 + 32);
            {
                unsigned af[4];
                const int8_t* ap = ap0 + k0;
                uint2 lo = *(const uint2*)ap;
                uint2 hi = *(const uint2*)(ap + 8 * SROW);
                af[0] = lo.x; af[2] = lo.y;
                af[1] = hi.x; af[3] = hi.y;
#pragma unroll
                for (int nt = 0; nt < 4; nt++) mma8(c[nt], af, V0[nt]);
            }
            if (k0 + 64 < Nn) pv_ldV(V0, vt0, k0 + 64);
            {
                unsigned af[4];
                const int8_t* ap = ap0 + k0 + 32;
                uint2 lo = *(const uint2*)ap;
                uint2 hi = *(const uint2*)(ap + 8 * SROW);
                af[0] = lo.x; af[2] = lo.y;
                af[1] = hi.x; af[3] = hi.y;
#pragma unroll
                for (int nt = 0; nt < 4; nt++) mma8(c[nt], af, V1[nt]);
            }
        }

        const float c3 = __ldg(al_attn2) * __ldg(al_v);
        const float ipa = c3 / __ldg(al_pa);
        const int b = bh / Hh, h = bh % Hh;
#pragma unroll
        for (int nt = 0; nt < 4; nt++)
#pragma unroll
            for (int j = 0; j < 4; j++) {
                int n = rb + wm2 + lr + ((j >> 1) << 3);
                int d = wn2 + nt * 8 + ((lane & 3) << 1) + (j & 1);
                g_o[(b * Nn + n) * Cc + h * Dd + PHYS32(d)] =
                    (int8_t)q8b((float)c[nt][j] * ipa);
            }
    }
}

// ---------------- GEMM2: 32x128 tiles (reuse-optimal), grid 384 ----------------
__device__ __forceinline__ void ldB4i(unsigned b[4][2], const int8_t* base, int k0) {
#pragma unroll
    for (int nt = 0; nt < 4; nt++) {
        uint2 bv = *(const uint2*)(base + nt * 8 * Cc + k0);
        b[nt][0] = bv.x; b[nt][1] = bv.y;
    }
}
__global__ void __launch_bounds__(256) gemm_proj_k(
    float* __restrict__ out, const float* __restrict__ bias,
    const float* al_pa, const float* al_pw) {
    const int bm = blockIdx.y * 32;
    const int bn = blockIdx.x * 128;
    const int wid = threadIdx.x >> 5;
    const int lane = threadIdx.x & 31;
    const int wm = (wid & 1) * 16;
    const int wn = (wid >> 1) * 32;
    const int lr = lane >> 2;
    const int q8 = (lane & 3) << 3;
    const int8_t* abase = g_o + (bm + wm + lr) * Cc + q8;
    const int8_t* bbase = g_wproj + (bn + wn + lr) * Cc + q8;

    int c[4][4];
#pragma unroll
    for (int j = 0; j < 4; j++)
#pragma unroll
        for (int t = 0; t < 4; t++) c[j][t] = 0;

    unsigned A0[4], A1[4], B0[4][2], B1[4][2];
    {
        uint2 lo = *(const uint2*)abase;
        uint2 hi = *(const uint2*)(abase + 8 * Cc);
        A0[0] = lo.x; A0[2] = lo.y; A0[1] = hi.x; A0[3] = hi.y;
    }
    ldB4i(B0, bbase, 0);
#pragma unroll 1
    for (int k0 = 0; k0 < Cc; k0 += 64) {
        {
            uint2 lo = *(const uint2*)(abase + k0 + 32);
            uint2 hi = *(const uint2*)(abase + k0 + 32 + 8 * Cc);
            A1[0] = lo.x; A1[2] = lo.y; A1[1] = hi.x; A1[3] = hi.y;
        }
        ldB4i(B1, bbase, k0 + 32);
#pragma unroll
        for (int nt = 0; nt < 4; nt++) mma8(c[nt], A0, B0[nt]);
        if (k0 + 64 < Cc) {
            uint2 lo = *(const uint2*)(abase + k0 + 64);
            uint2 hi = *(const uint2*)(abase + k0 + 64 + 8 * Cc);
            A0[0] = lo.x; A0[2] = lo.y; A0[1] = hi.x; A0[3] = hi.y;
            ldB4i(B0, bbase, k0 + 64);
        }
#pragma unroll
        for (int nt = 0; nt < 4; nt++) mma8(c[nt], A1, B1[nt]);
    }

    const float sc = __ldg(al_pa) * __ldg(al_pw);
#pragma unroll
    for (int nt = 0; nt < 4; nt++)
#pragma unroll
        for (int j = 0; j < 4; j++) {
            int row = bm + wm + lr + ((j >> 1) << 3);
            int col = bn + wn + nt * 8 + ((lane & 3) << 1) + (j & 1);
            out[row * Cc + col] = (float)c[nt][j] * sc + __ldg(bias + col);
        }
}

extern "C" void kernel_launch(void* const* d_in, const int* in_sizes, int n_in,
                              void* d_out, int out_size) {
    const float* x        = (const float*)d_in[0];
    const float* w_qkv    = (const float*)d_in[1];
    const float* w_proj   = (const float*)d_in[2];
    const float* b_proj   = (const float*)d_in[3];
    const float* a_qkv_w  = (const float*)d_in[4];
    const float* a_qkv_a  = (const float*)d_in[5];
    const float* a_proj_w = (const float*)d_in[6];
    const float* a_proj_a = (const float*)d_in[7];
    const float* a_q      = (const float*)d_in[8];
    const float* a_k      = (const float*)d_in[9];
    const float* a_v      = (const float*)d_in[10];
    const float* a_attn   = (const float*)d_in[11];
    const float* a_attn2  = (const float*)d_in[12];
    float* out = (float*)d_out;

    quant_all_k<<<2112, 256>>>(x, w_qkv, w_proj, a_qkv_a, a_qkv_w, a_proj_w);

    gemm_qkv_k<<<dim3(C3 / 128, BN / 128), 256>>>(a_qkv_a, a_qkv_w, a_q, a_k, a_v);

    cudaFuncSetAttribute(attn_fused_k, cudaFuncAttributeMaxDynamicSharedMemorySize, SMEM_SZ);
    attn_fused_k<<<dim3(Nn / 32, BHh), 128, SMEM_SZ>>>(a_q, a_k, a_attn, a_attn2, a_v, a_proj_a);

    gemm_proj_k<<<dim3(Cc / 128, BN / 32), 256>>>(out, b_proj, a_proj_a, a_proj_w);
}